// round 5
// baseline (speedup 1.0000x reference)
#include <cuda_runtime.h>
#include <cuda_bf16.h>
#include <cstdint>

// ============================================================================
// IsingRBM: psi[m] = prod_h cos(bias[h] + (x@W1)[m,h] + 0.5 * x^T W2[h] x)
// mma.sync.m16n8k16 bf16 (compute_103 baseline PTX; tcgen05 unavailable).
//
// Symmetric K-packing (upper triangle, rows 16-aligned): 164 k16-blocks in
// 41 chunks of 64 k; compile-time schedule (regions A..E, see R4 notes).
// R5: kill exposed latency inside the chunk body —
//   * kb-loop software-pipelined by 1 (LDSM/scale loads for kb+1 issue
//     under kb's MMAs; R4 re-exposed LDSM latency 4x per chunk)
//   * per-thread scale quadruples pre-gathered into xq -> 4 LDS.128 per
//     chunk instead of 16 LDS.32
//   * cp.async offsets hoisted out of the loop
// 256 threads / CTA, M-tile 64, 2 CTAs per SM.
// ============================================================================

static constexpr int kV = 64;
static constexpr int kH = 128;
static constexpr int kMTile = 64;
static constexpr int kChunks = 41;
static constexpr int kChunkBytes = kH * kV * 2;   // 16384
static constexpr int kThreads = 256;

// smem layout (bytes, relative to 1024-aligned base)
static constexpr int SM_BIAS = 0;                  // 128 f32
static constexpr int SM_PART = 512;                // 64*4 f32 = 1024
static constexpr int SM_XQ   = 1536;               // 64*16 uint4 = 16384
static constexpr int SM_XT   = 18432;              // 64x64 bf16 SW128 = 8192 (1024-al)
static constexpr int SM_B    = 27648;              // 3 * 16384 (1024-al)
static constexpr int SM_END  = SM_B + 3 * kChunkBytes;   // 76800
static constexpr int SMEM_TOTAL = SM_END + 1024;   // 77824 (x2 CTAs = 152K < 228K)

// Packed B operand: [chunk][h][64] bf16, cols = 4 k16-blocks per chunk.
__device__ __align__(16) __nv_bfloat16 g_wb[kChunks * kH * kV];

// ---------------------------------------------------------------------------
// helpers
// ---------------------------------------------------------------------------
__device__ __forceinline__ uint32_t smem_u32(const void* p) {
    uint32_t a;
    asm("{ .reg .u64 t; cvta.to.shared.u64 t, %1; cvt.u32.u64 %0, t; }"
        : "=r"(a) : "l"(p));
    return a;
}

#define SW128(o) ((o) ^ (((o) >> 3) & 0x70))

#define CVT_BF16X2(result, a, b) \
    asm("cvt.rn.bf16x2.f32 %0, %1, %2;" : "=r"(result) : "f"(b), "f"(a))

#define HMUL2(d, a, b) \
    asm("mul.rn.bf16x2 %0, %1, %2;" : "=r"(d) : "r"(a), "r"(b))

#define LDSM_X4(r0, r1, r2, r3, addr) \
    asm volatile("ldmatrix.sync.aligned.m8n8.x4.shared.b16 {%0,%1,%2,%3}, [%4];" \
        : "=r"(r0), "=r"(r1), "=r"(r2), "=r"(r3) : "r"(addr))

#define MMA16816(d, a0, a1, a2, a3, b0, b1) \
    asm volatile("mma.sync.aligned.m16n8k16.row.col.f32.bf16.bf16.f32 " \
        "{%0,%1,%2,%3}, {%4,%5,%6,%7}, {%8,%9}, {%0,%1,%2,%3};" \
        : "+f"((d)[0]), "+f"((d)[1]), "+f"((d)[2]), "+f"((d)[3]) \
        : "r"(a0), "r"(a1), "r"(a2), "r"(a3), "r"(b0), "r"(b1))

#define CP_ASYNC16(smem, gmem) \
    asm volatile("cp.async.cg.shared.global [%0], [%1], 16;" \
        :: "r"(smem), "l"(gmem) : "memory")
#define CP_COMMIT() asm volatile("cp.async.commit_group;" ::: "memory")
#define CP_WAIT1()  asm volatile("cp.async.wait_group 1;" ::: "memory")

__device__ __forceinline__ float cos_poly(float a) {
    // |a| < 0.1 guaranteed by problem statistics; deg-8 Taylor, err < 1e-12
    float t = a * a;
    return 1.0f + t * (-0.5f + t * (4.16666667e-2f +
               t * (-1.38888889e-3f + t * 2.48015873e-5f)));
}

// block schedule decode — used ONLY by the one-shot prep kernel
__device__ __forceinline__ int decode_i(int b) {
    if (b < 64)  return b >> 2;
    if (b < 112) return 16 + (b - 64) / 3;
    if (b < 144) return 32 + ((b - 112) >> 1);
    if (b < 160) return 48 + (b - 144);
    return 64;
}
__device__ __forceinline__ int decode_kbf(int b) {
    if (b < 64)  return b & 3;
    if (b < 112) return 1 + (b - 64) % 3;
    if (b < 144) return 2 + ((b - 112) & 1);
    if (b < 160) return 3;
    return b - 160;
}

// ---------------------------------------------------------------------------
// prep: build packed bf16 B operand g_wb from W2 (f32) + 2*W1^T (f32)
// ---------------------------------------------------------------------------
__global__ void __launch_bounds__(256) prep_kernel(const float* __restrict__ w2,
                                                   const float* __restrict__ w1) {
    int t = blockIdx.x * blockDim.x + threadIdx.x;
    int e = t * 4;
    if (e >= kChunks * kH * kV) return;
    int c   = e >> 13;
    int rem = e & 8191;
    int h   = rem >> 6;
    int col = rem & 63;
    int b   = 4 * c + (col >> 4);
    int i   = decode_i(b);
    int kbf = decode_kbf(b);
    int j0  = kbf * 16 + (col & 15);
    float v[4];
    #pragma unroll
    for (int q = 0; q < 4; q++) {
        int j = j0 + q;
        if (i == 64)     v[q] = 2.0f * w1[j * kH + h];
        else if (j > i)  v[q] = w2[h * 4096 + i * 64 + j] + w2[h * 4096 + j * 64 + i];
        else if (j == i) v[q] = w2[h * 4096 + i * 64 + j];
        else             v[q] = 0.0f;
    }
    uint32_t lo, hi;
    CVT_BF16X2(lo, v[0], v[1]);
    CVT_BF16X2(hi, v[2], v[3]);
    reinterpret_cast<uint2*>(g_wb)[t] = make_uint2(lo, hi);
}

// ---------------------------------------------------------------------------
// chunk body: kbf + i-delta patterns compile-time; software-pipelined by 1 kb
// xq4: per-thread scale base (xq + grp*4), j-stride = 64 u32; one LDS.128
// yields the 4 broadcast scales for rows rb0+{0,8,16,24}.
// ---------------------------------------------------------------------------
template<int K0, int K1, int K2, int K3, int D0, int D1, int D2, int D3, bool LIN>
__device__ __forceinline__ void do_chunk(
    uint32_t bb, const uint32_t* __restrict__ boff,
    const uint32_t (&abase)[2][4][4],
    const uint32_t* __restrict__ xq4, int ibase,
    float (&acc)[2][4][4])
{
    const int KF[4] = {K0, K1, K2, K3};
    const int DI[4] = {D0, D1, D2, D3};
    uint32_t bf[2][4][2];
    uint32_t sv[2][4];

    // preload kb = 0
    LDSM_X4(bf[0][0][0], bf[0][0][1], bf[0][1][0], bf[0][1][1], bb + boff[0]);
    LDSM_X4(bf[0][2][0], bf[0][2][1], bf[0][3][0], bf[0][3][1], bb + boff[1]);
    if (LIN) {
        sv[0][0] = sv[0][1] = sv[0][2] = sv[0][3] = 0x3F803F80u;
    } else {
        uint4 s = *reinterpret_cast<const uint4*>(xq4 + (ibase + DI[0]) * 64);
        sv[0][0] = s.x; sv[0][1] = s.y; sv[0][2] = s.z; sv[0][3] = s.w;
    }

    #pragma unroll
    for (int kb = 0; kb < 4; kb++) {
        const int cur = kb & 1, nxt = cur ^ 1;
        if (kb < 3) {   // issue kb+1's loads under kb's MMAs
            LDSM_X4(bf[nxt][0][0], bf[nxt][0][1], bf[nxt][1][0], bf[nxt][1][1],
                    bb + boff[2 * (kb + 1)]);
            LDSM_X4(bf[nxt][2][0], bf[nxt][2][1], bf[nxt][3][0], bf[nxt][3][1],
                    bb + boff[2 * (kb + 1) + 1]);
            if (LIN) {
                sv[nxt][0] = sv[nxt][1] = sv[nxt][2] = sv[nxt][3] = 0x3F803F80u;
            } else {
                uint4 s = *reinterpret_cast<const uint4*>(
                    xq4 + (ibase + DI[kb + 1]) * 64);
                sv[nxt][0] = s.x; sv[nxt][1] = s.y; sv[nxt][2] = s.z; sv[nxt][3] = s.w;
            }
        }
        #pragma unroll
        for (int mb = 0; mb < 2; mb++) {
            uint32_t t0, t1, t2, t3;
            HMUL2(t0, abase[mb][KF[kb]][0], sv[cur][2 * mb]);      // rows g
            HMUL2(t1, abase[mb][KF[kb]][1], sv[cur][2 * mb + 1]);  // rows g+8
            HMUL2(t2, abase[mb][KF[kb]][2], sv[cur][2 * mb]);
            HMUL2(t3, abase[mb][KF[kb]][3], sv[cur][2 * mb + 1]);
            #pragma unroll
            for (int nb = 0; nb < 4; nb++)
                MMA16816(acc[mb][nb], t0, t1, t2, t3,
                         bf[cur][nb][0], bf[cur][nb][1]);
        }
    }
}

// ---------------------------------------------------------------------------
// main fused kernel: 64-row M-tile per CTA, H=128 as N, 8 warps (2M x 4N),
// 2 CTAs per SM
// ---------------------------------------------------------------------------
__global__ void __launch_bounds__(kThreads, 2)
rbm_main_kernel(const float* __restrict__ x,
                const float* __restrict__ bias,
                float* __restrict__ out) {
    extern __shared__ char smem_raw[];
    char* sm = (char*)((((uintptr_t)smem_raw) + 1023) & ~(uintptr_t)1023);
    const uint32_t sb = smem_u32(sm);
    const int tid = threadIdx.x;
    const int l   = tid & 31;
    const int w   = tid >> 5;
    const int g   = l >> 2;
    const int t4  = l & 3;
    const int wm  = (w >> 2) * 32;     // warp M offset (0,32)
    const int wn  = (w & 3) * 32;      // warp N offset (0,32,64,96)
    const int m0  = blockIdx.x * kMTile;

    float*    sbias = (float*)(sm + SM_BIAS);
    float*    spart = (float*)(sm + SM_PART);
    uint32_t* xq    = (uint32_t*)(sm + SM_XQ);    // [j][16 grp][4] u32

    if (tid < kH) sbias[tid] = bias[tid];

    // --- x bf16 tile [m][j], 128B rows, SW128 swizzled (A ldmatrix source) ---
    {
        const float4* x4 = (const float4*)(x + (size_t)m0 * kV);
        #pragma unroll
        for (int e = tid; e < kMTile * 16; e += kThreads) {   // 64 rows * 16 float4
            int r = e >> 4, q = e & 15;
            float4 f = x4[e];
            uint32_t u0, u1;
            CVT_BF16X2(u0, f.x, f.y);
            CVT_BF16X2(u1, f.z, f.w);
            uint32_t off = (uint32_t)(r * 128 + q * 8);
            *(uint2*)(sm + SM_XT + SW128(off)) = make_uint2(u0, u1);
        }
    }
    // --- xq[j][grp][k] = bf16x2 broadcast of x[m0 + mbase(grp) + 8k][j] ---
    //     mbase(grp) = grp (grp<8) | grp+24 (grp>=8)    (wm=0 / wm=32 warps)
    #pragma unroll
    for (int e = tid; e < kV * 16 * 4; e += kThreads) {   // 4096 entries
        int j   = e >> 6;
        int grp = (e >> 2) & 15;
        int k   = e & 3;
        int m   = ((grp < 8) ? grp : grp + 24) + 8 * k;
        float v = x[(size_t)(m0 + m) * kV + j];
        uint32_t p;
        CVT_BF16X2(p, v, v);
        xq[e] = p;
    }

    // --- cp.async offsets (hoisted): 4 x 16B per thread per chunk ---
    uint32_t cp_raw[4], cp_dst[4];
    #pragma unroll
    for (int p = 0; p < 4; p++) {
        int cg = tid + p * kThreads;
        cp_raw[p] = (uint32_t)((cg >> 3) * 128 + (cg & 7) * 16);
        cp_dst[p] = SW128(cp_raw[p]);
    }
    const char* gw = (const char*)g_wb;
    #define ISSUE_CHUNK(c, buf) do {                                          \
        const char* _src = gw + (size_t)(c) * kChunkBytes;                    \
        uint32_t _dst = sb + SM_B + (uint32_t)(buf) * kChunkBytes;            \
        _Pragma("unroll")                                                     \
        for (int _p = 0; _p < 4; _p++)                                        \
            CP_ASYNC16(_dst + cp_dst[_p], _src + cp_raw[_p]);                 \
    } while (0)

    ISSUE_CHUNK(0, 0); CP_COMMIT();
    ISSUE_CHUNK(1, 1); CP_COMMIT();

    __syncthreads();   // x tiles + bias ready

    // --- A-base fragments (warp's 32x64 x-tile) in registers ---
    uint32_t abase[2][4][4];
    {
        int q = l >> 3, rr = l & 7;
        #pragma unroll
        for (int mb = 0; mb < 2; mb++)
        #pragma unroll
        for (int kb = 0; kb < 4; kb++) {
            uint32_t off = (uint32_t)((wm + 16 * mb + (q & 1) * 8 + rr) * 128
                                      + (kb * 16 + (q >> 1) * 8) * 2);
            LDSM_X4(abase[mb][kb][0], abase[mb][kb][1],
                    abase[mb][kb][2], abase[mb][kb][3],
                    sb + SM_XT + SW128(off));
        }
    }

    // --- per-thread B ldmatrix offsets (swizzled, rel. to buffer base) ---
    uint32_t boff[8];
    {
        int q = l >> 3, rr = l & 7;
        #pragma unroll
        for (int kb = 0; kb < 4; kb++)
        #pragma unroll
        for (int nb2 = 0; nb2 < 2; nb2++) {
            uint32_t off = (uint32_t)((wn + nb2 * 16 + (q >> 1) * 8 + rr) * 128
                                      + (kb * 16 + (q & 1) * 8) * 2);
            boff[kb * 2 + nb2] = SW128(off);
        }
    }

    float acc[2][4][4];
    #pragma unroll
    for (int a = 0; a < 2; a++)
    #pragma unroll
    for (int b = 0; b < 4; b++)
    #pragma unroll
    for (int c = 0; c < 4; c++) acc[a][b][c] = 0.0f;

    const int rb0  = wm + g;
    const uint32_t* xq4 = xq + ((wm >> 2) + g) * 4;   // grp = (wm>>2)+g

    // pipeline step: wait chunk c, release buffer (c+2)%3, prefetch c+2, body
    int c = 0;
    #define PIPE(BODY) do {                                                   \
        CP_WAIT1();                                                           \
        __syncthreads();                                                      \
        if (c + 2 < kChunks) { ISSUE_CHUNK(c + 2, (c + 2) % 3); }             \
        CP_COMMIT();                                                          \
        uint32_t bb = sb + SM_B + (uint32_t)(c % 3) * kChunkBytes;            \
        BODY;                                                                 \
        c++;                                                                  \
    } while (0)

    // Region A: i = c, kbf 0..3
    #pragma unroll 1
    for (int cc = 0; cc < 16; cc++) {
        PIPE((do_chunk<0,1,2,3, 0,0,0,0, false>(bb, boff, abase, xq4, cc, acc)));
    }
    // Region B: 3-chunk period, i 16..31
    int I = 16;
    #pragma unroll 1
    for (int r = 0; r < 4; r++) {
        PIPE((do_chunk<1,2,3,1, 0,0,0,1, false>(bb, boff, abase, xq4, I,     acc)));
        PIPE((do_chunk<2,3,1,2, 0,0,1,1, false>(bb, boff, abase, xq4, I + 1, acc)));
        PIPE((do_chunk<3,1,2,3, 0,1,1,1, false>(bb, boff, abase, xq4, I + 2, acc)));
        I += 4;
    }
    // Region C: i 32..47
    #pragma unroll 1
    for (int r = 0; r < 8; r++) {
        PIPE((do_chunk<2,3,2,3, 0,0,1,1, false>(bb, boff, abase, xq4, I, acc)));
        I += 2;
    }
    // Region D: i 48..63
    #pragma unroll 1
    for (int r = 0; r < 4; r++) {
        PIPE((do_chunk<3,3,3,3, 0,1,2,3, false>(bb, boff, abase, xq4, I, acc)));
        I += 4;
    }
    // Region E: linear term
    PIPE((do_chunk<0,1,2,3, 0,0,0,0, true>(bb, boff, abase, xq4, 0, acc)));

    // --- epilogue: a = bias + 0.5*acc; psi = prod cos(a) ---
    #pragma unroll
    for (int mb = 0; mb < 2; mb++) {
        float p0 = 1.0f, p1 = 1.0f;
        #pragma unroll
        for (int nb = 0; nb < 4; nb++) {
            int col = wn + nb * 8 + 2 * t4;
            #pragma unroll
            for (int cc = 0; cc < 2; cc++) {
                float bv = sbias[col + cc];
                p0 *= cos_poly(bv + 0.5f * acc[mb][nb][cc]);       // row g
                p1 *= cos_poly(bv + 0.5f * acc[mb][nb][2 + cc]);   // row g+8
            }
        }
        p0 *= __shfl_xor_sync(0xFFFFFFFFu, p0, 1);
        p0 *= __shfl_xor_sync(0xFFFFFFFFu, p0, 2);
        p1 *= __shfl_xor_sync(0xFFFFFFFFu, p1, 1);
        p1 *= __shfl_xor_sync(0xFFFFFFFFu, p1, 2);
        if (t4 == 0) {
            spart[(rb0 + 16 * mb) * 4 + (w & 3)]     = p0;
            spart[(rb0 + 16 * mb + 8) * 4 + (w & 3)] = p1;
        }
    }
    __syncthreads();
    if (tid < kMTile) {
        out[m0 + tid] = spart[tid * 4 + 0] * spart[tid * 4 + 1]
                      * spart[tid * 4 + 2] * spart[tid * 4 + 3];
    }
}

// ---------------------------------------------------------------------------
// launch
// ---------------------------------------------------------------------------
extern "C" void kernel_launch(void* const* d_in, const int* in_sizes, int n_in,
                              void* d_out, int out_size) {
    const float* x    = (const float*)d_in[0];   // (16384, 64)
    const float* w1   = (const float*)d_in[1];   // (64, 128)
    const float* w2   = (const float*)d_in[2];   // (128, 64, 64)
    const float* bias = (const float*)d_in[3];   // (128,)
    float* out = (float*)d_out;                  // (16384,)

    cudaFuncSetAttribute(rbm_main_kernel,
                         cudaFuncAttributeMaxDynamicSharedMemorySize, SMEM_TOTAL);

    prep_kernel<<<328, 256>>>(w2, w1);           // 41*8192/4/256
    rbm_main_kernel<<<16384 / kMTile, kThreads, SMEM_TOTAL>>>(x, bias, out);
}

// round 6
// speedup vs baseline: 1.0549x; 1.0549x over previous
#include <cuda_runtime.h>
#include <cuda_bf16.h>
#include <cstdint>

// ============================================================================
// IsingRBM: psi[m] = prod_h cos(bias[h] + (x@W1)[m,h] + 0.5 * x^T W2[h] x)
// mma.sync.m16n8k16 bf16 (compute_103 baseline PTX; tcgen05 unavailable).
//
// Symmetric K-packing (upper triangle, rows 16-aligned): 164 k16-blocks in
// 41 chunks of 64 k; compile-time schedule (regions A..E).
// R6: barrier every FOUR chunks instead of every chunk.
//   * 1 CTA x 512 threads (M-tile 128, warp grid 4Mx4N) -> smem budget for
//     8 B-buffers (128 KB).  Quad step: __syncthreads -> issue 4 chunks
//     (cp.async) -> wait_group 4 -> 4 chunk bodies with NO interior syncs,
//     letting ptxas overlap chunk c+1's LDSMs under chunk c's MMAs.
//   * exactly 4 commits per quad (empty at tail) keeps wait_group 4 sound.
//   * R5's reg-starved kb-pipelining reverted; its vectorized scale load
//     (one LDS.128 per kb) kept.
// ============================================================================

static constexpr int kV = 64;
static constexpr int kH = 128;
static constexpr int kMTile = 128;
static constexpr int kChunks = 41;
static constexpr int kChunkBytes = kH * kV * 2;   // 16384
static constexpr int kThreads = 512;
static constexpr int kNBuf = 8;

// smem layout (bytes, relative to 1024-aligned base)
static constexpr int SM_BIAS = 0;                  // 128 f32
static constexpr int SM_PART = 512;                // 128*4 f32 = 2048
static constexpr int SM_XQ   = 2560;               // 64 j * 32 grp * 4 u32 = 32768
static constexpr int SM_B    = 35840;              // 8 * 16384 (1024-aligned)
static constexpr int SM_XT   = SM_B + 4 * kChunkBytes;   // overlay on buf 4 (16 KB)
static constexpr int SM_END  = SM_B + kNBuf * kChunkBytes;      // 166912
static constexpr int SMEM_TOTAL = SM_END + 1024;   // 167936 < 227 KB

// Packed B operand: [chunk][h][64] bf16, cols = 4 k16-blocks per chunk.
__device__ __align__(16) __nv_bfloat16 g_wb[kChunks * kH * kV];

// ---------------------------------------------------------------------------
// helpers
// ---------------------------------------------------------------------------
__device__ __forceinline__ uint32_t smem_u32(const void* p) {
    uint32_t a;
    asm("{ .reg .u64 t; cvta.to.shared.u64 t, %1; cvt.u32.u64 %0, t; }"
        : "=r"(a) : "l"(p));
    return a;
}

#define SW128(o) ((o) ^ (((o) >> 3) & 0x70))

#define CVT_BF16X2(result, a, b) \
    asm("cvt.rn.bf16x2.f32 %0, %1, %2;" : "=r"(result) : "f"(b), "f"(a))

#define HMUL2(d, a, b) \
    asm("mul.rn.bf16x2 %0, %1, %2;" : "=r"(d) : "r"(a), "r"(b))

#define LDSM_X4(r0, r1, r2, r3, addr) \
    asm volatile("ldmatrix.sync.aligned.m8n8.x4.shared.b16 {%0,%1,%2,%3}, [%4];" \
        : "=r"(r0), "=r"(r1), "=r"(r2), "=r"(r3) : "r"(addr))

#define MMA16816(d, a0, a1, a2, a3, b0, b1) \
    asm volatile("mma.sync.aligned.m16n8k16.row.col.f32.bf16.bf16.f32 " \
        "{%0,%1,%2,%3}, {%4,%5,%6,%7}, {%8,%9}, {%0,%1,%2,%3};" \
        : "+f"((d)[0]), "+f"((d)[1]), "+f"((d)[2]), "+f"((d)[3]) \
        : "r"(a0), "r"(a1), "r"(a2), "r"(a3), "r"(b0), "r"(b1))

#define CP_ASYNC16(smem, gmem) \
    asm volatile("cp.async.cg.shared.global [%0], [%1], 16;" \
        :: "r"(smem), "l"(gmem) : "memory")
#define CP_COMMIT() asm volatile("cp.async.commit_group;" ::: "memory")
#define CP_WAIT4()  asm volatile("cp.async.wait_group 4;" ::: "memory")

__device__ __forceinline__ float cos_poly(float a) {
    // |a| < 0.1 guaranteed by problem statistics; deg-8 Taylor, err < 1e-12
    float t = a * a;
    return 1.0f + t * (-0.5f + t * (4.16666667e-2f +
               t * (-1.38888889e-3f + t * 2.48015873e-5f)));
}

// block schedule decode — used ONLY by the one-shot prep kernel
__device__ __forceinline__ int decode_i(int b) {
    if (b < 64)  return b >> 2;
    if (b < 112) return 16 + (b - 64) / 3;
    if (b < 144) return 32 + ((b - 112) >> 1);
    if (b < 160) return 48 + (b - 144);
    return 64;
}
__device__ __forceinline__ int decode_kbf(int b) {
    if (b < 64)  return b & 3;
    if (b < 112) return 1 + (b - 64) % 3;
    if (b < 144) return 2 + ((b - 112) & 1);
    if (b < 160) return 3;
    return b - 160;
}

// ---------------------------------------------------------------------------
// prep: build packed bf16 B operand g_wb from W2 (f32) + 2*W1^T (f32)
// ---------------------------------------------------------------------------
__global__ void __launch_bounds__(256) prep_kernel(const float* __restrict__ w2,
                                                   const float* __restrict__ w1) {
    int t = blockIdx.x * blockDim.x + threadIdx.x;
    int e = t * 4;
    if (e >= kChunks * kH * kV) return;
    int c   = e >> 13;
    int rem = e & 8191;
    int h   = rem >> 6;
    int col = rem & 63;
    int b   = 4 * c + (col >> 4);
    int i   = decode_i(b);
    int kbf = decode_kbf(b);
    int j0  = kbf * 16 + (col & 15);
    float v[4];
    #pragma unroll
    for (int q = 0; q < 4; q++) {
        int j = j0 + q;
        if (i == 64)     v[q] = 2.0f * w1[j * kH + h];
        else if (j > i)  v[q] = w2[h * 4096 + i * 64 + j] + w2[h * 4096 + j * 64 + i];
        else if (j == i) v[q] = w2[h * 4096 + i * 64 + j];
        else             v[q] = 0.0f;
    }
    uint32_t lo, hi;
    CVT_BF16X2(lo, v[0], v[1]);
    CVT_BF16X2(hi, v[2], v[3]);
    reinterpret_cast<uint2*>(g_wb)[t] = make_uint2(lo, hi);
}

// ---------------------------------------------------------------------------
// chunk body (R4 structure): kbf + i-delta patterns compile-time.
// xq4: per-thread scale base; one LDS.128 per kb yields 4 broadcast scales
// for rows rb0+{0,8,16,24}; j-stride = 128 u32.
// ---------------------------------------------------------------------------
template<int K0, int K1, int K2, int K3, int D0, int D1, int D2, int D3, bool LIN>
__device__ __forceinline__ void do_chunk(
    uint32_t bb, const uint32_t* __restrict__ boff,
    const uint32_t (&abase)[2][4][4],
    const uint32_t* __restrict__ xq4, int ibase,
    float (&acc)[2][4][4])
{
    const int KF[4] = {K0, K1, K2, K3};
    const int DI[4] = {D0, D1, D2, D3};
    #pragma unroll
    for (int kb = 0; kb < 4; kb++) {
        uint32_t sv[4];
        if (LIN) {
            sv[0] = sv[1] = sv[2] = sv[3] = 0x3F803F80u;   // bf16x2(1,1)
        } else {
            uint4 s = *reinterpret_cast<const uint4*>(
                xq4 + (ibase + DI[kb]) * 128);
            sv[0] = s.x; sv[1] = s.y; sv[2] = s.z; sv[3] = s.w;
        }
        uint32_t bf[4][2];
        LDSM_X4(bf[0][0], bf[0][1], bf[1][0], bf[1][1], bb + boff[kb * 2 + 0]);
        LDSM_X4(bf[2][0], bf[2][1], bf[3][0], bf[3][1], bb + boff[kb * 2 + 1]);
        #pragma unroll
        for (int mb = 0; mb < 2; mb++) {
            uint32_t t0, t1, t2, t3;
            HMUL2(t0, abase[mb][KF[kb]][0], sv[2 * mb]);      // rows g
            HMUL2(t1, abase[mb][KF[kb]][1], sv[2 * mb + 1]);  // rows g+8
            HMUL2(t2, abase[mb][KF[kb]][2], sv[2 * mb]);
            HMUL2(t3, abase[mb][KF[kb]][3], sv[2 * mb + 1]);
            #pragma unroll
            for (int nb = 0; nb < 4; nb++)
                MMA16816(acc[mb][nb], t0, t1, t2, t3, bf[nb][0], bf[nb][1]);
        }
    }
}

// ---------------------------------------------------------------------------
// main fused kernel: 128-row M-tile per CTA, H=128 as N, 16 warps (4M x 4N),
// 1 CTA per SM, 8 B-buffers, barrier every 4 chunks
// ---------------------------------------------------------------------------
__global__ void __launch_bounds__(kThreads, 1)
rbm_main_kernel(const float* __restrict__ x,
                const float* __restrict__ bias,
                float* __restrict__ out) {
    extern __shared__ char smem_raw[];
    char* sm = (char*)((((uintptr_t)smem_raw) + 1023) & ~(uintptr_t)1023);
    const uint32_t sb = smem_u32(sm);
    const int tid = threadIdx.x;
    const int l   = tid & 31;
    const int w   = tid >> 5;
    const int g   = l >> 2;
    const int t4  = l & 3;
    const int wm  = (w >> 2) * 32;     // warp M offset (0,32,64,96)
    const int wn  = (w & 3) * 32;      // warp N offset (0,32,64,96)
    const int m0  = blockIdx.x * kMTile;

    float*    sbias = (float*)(sm + SM_BIAS);
    float*    spart = (float*)(sm + SM_PART);
    uint32_t* xq    = (uint32_t*)(sm + SM_XQ);    // [j][32 grp][4 k] u32

    if (tid < kH) sbias[tid] = bias[tid];

    // --- x bf16 tile [m][j], 128B rows, SW128 swizzled (A ldmatrix source) ---
    // lives in buffer-4 space; consumed (abase LDSM) before the first quad
    // barrier, after which cp.async may overwrite it.
    {
        const float4* x4 = (const float4*)(x + (size_t)m0 * kV);
        #pragma unroll
        for (int e = tid; e < kMTile * 16; e += kThreads) {   // 128 rows * 16 float4
            int r = e >> 4, q = e & 15;
            float4 f = x4[e];
            uint32_t u0, u1;
            CVT_BF16X2(u0, f.x, f.y);
            CVT_BF16X2(u1, f.z, f.w);
            uint32_t off = (uint32_t)(r * 128 + q * 8);
            *(uint2*)(sm + SM_XT + SW128(off)) = make_uint2(u0, u1);
        }
    }
    // --- xq[j][grp][k] = bf16x2 broadcast of x[m0 + mb(grp) + 8k][j] ---
    //     mb(grp) = (grp>>3)*32 + (grp&7)
    #pragma unroll
    for (int e = tid; e < kV * 32 * 4; e += kThreads) {   // 8192 entries
        int j   = e >> 7;
        int grp = (e >> 2) & 31;
        int k   = e & 3;
        int m   = (grp >> 3) * 32 + (grp & 7) + 8 * k;
        float v = x[(size_t)(m0 + m) * kV + j];
        uint32_t p;
        CVT_BF16X2(p, v, v);
        xq[e] = p;
    }

    // --- cp.async offsets (hoisted): 2 x 16B per thread per chunk ---
    uint32_t cp_raw[2], cp_dst[2];
    #pragma unroll
    for (int p = 0; p < 2; p++) {
        int cg = tid + p * kThreads;
        cp_raw[p] = (uint32_t)((cg >> 3) * 128 + (cg & 7) * 16);
        cp_dst[p] = SW128(cp_raw[p]);
    }
    const char* gw = (const char*)g_wb;
    #define ISSUE_CHUNK(c, buf) do {                                          \
        const char* _src = gw + (size_t)(c) * kChunkBytes;                    \
        uint32_t _dst = sb + SM_B + (uint32_t)(buf) * kChunkBytes;            \
        CP_ASYNC16(_dst + cp_dst[0], _src + cp_raw[0]);                       \
        CP_ASYNC16(_dst + cp_dst[1], _src + cp_raw[1]);                       \
    } while (0)

    // prologue: chunks 0..3 into buffers 0..3 (one group each)
    #pragma unroll
    for (int p = 0; p < 4; p++) { ISSUE_CHUNK(p, p); CP_COMMIT(); }

    __syncthreads();   // x tiles + bias ready

    // --- A-base fragments (warp's 32x64 x-tile) in registers ---
    uint32_t abase[2][4][4];
    {
        int q = l >> 3, rr = l & 7;
        #pragma unroll
        for (int mb = 0; mb < 2; mb++)
        #pragma unroll
        for (int kb = 0; kb < 4; kb++) {
            uint32_t off = (uint32_t)((wm + 16 * mb + (q & 1) * 8 + rr) * 128
                                      + (kb * 16 + (q >> 1) * 8) * 2);
            LDSM_X4(abase[mb][kb][0], abase[mb][kb][1],
                    abase[mb][kb][2], abase[mb][kb][3],
                    sb + SM_XT + SW128(off));
        }
    }

    // --- per-thread B ldmatrix offsets (swizzled, rel. to buffer base) ---
    uint32_t boff[8];
    {
        int q = l >> 3, rr = l & 7;
        #pragma unroll
        for (int kb = 0; kb < 4; kb++)
        #pragma unroll
        for (int nb2 = 0; nb2 < 2; nb2++) {
            uint32_t off = (uint32_t)((wn + nb2 * 16 + (q >> 1) * 8 + rr) * 128
                                      + (kb * 16 + (q & 1) * 8) * 2);
            boff[kb * 2 + nb2] = SW128(off);
        }
    }

    float acc[2][4][4];
    #pragma unroll
    for (int a = 0; a < 2; a++)
    #pragma unroll
    for (int b = 0; b < 4; b++)
    #pragma unroll
    for (int c = 0; c < 4; c++) acc[a][b][c] = 0.0f;

    const int rb0 = wm + g;
    const uint32_t* xq4 = xq + ((wm >> 3 << 3) + g) * 4;   // grp = (wm>>2)/... = wm/4? see below
    // grp = (wm>>2) ... careful: grp index = (wm/32)*8 + g = (wm>>2) + g only
    // when wm in {0,32}: for wm in {0,32,64,96}, (wm>>2) = {0,8,16,24} — correct:
    const uint32_t* xq4c = xq + ((wm >> 2) + g) * 4;

    // quad pipeline step: every 4th chunk: barrier (buffers of chunks c-4..c-1
    // now reusable by ALL warps) -> issue chunks c+4..c+7 (exactly 4 commits)
    // -> wait_group 4 (chunks c..c+3 landed).
    int c = 0;
    #define PIPE(BODY) do {                                                   \
        if ((c & 3) == 0) {                                                   \
            __syncthreads();                                                  \
            _Pragma("unroll")                                                 \
            for (int _q = 0; _q < 4; _q++) {                                  \
                if (c + 4 + _q < kChunks)                                     \
                    ISSUE_CHUNK(c + 4 + _q, (c + 4 + _q) & 7);                \
                CP_COMMIT();                                                  \
            }                                                                 \
            CP_WAIT4();                                                       \
        }                                                                     \
        uint32_t bb = sb + SM_B + (uint32_t)(c & 7) * kChunkBytes;            \
        BODY;                                                                 \
        c++;                                                                  \
    } while (0)

    // Region A: i = c, kbf 0..3
    #pragma unroll 1
    for (int cc = 0; cc < 16; cc++) {
        PIPE((do_chunk<0,1,2,3, 0,0,0,0, false>(bb, boff, abase, xq4c, cc, acc)));
    }
    // Region B: 3-chunk period, i 16..31
    int I = 16;
    #pragma unroll 1
    for (int r = 0; r < 4; r++) {
        PIPE((do_chunk<1,2,3,1, 0,0,0,1, false>(bb, boff, abase, xq4c, I,     acc)));
        PIPE((do_chunk<2,3,1,2, 0,0,1,1, false>(bb, boff, abase, xq4c, I + 1, acc)));
        PIPE((do_chunk<3,1,2,3, 0,1,1,1, false>(bb, boff, abase, xq4c, I + 2, acc)));
        I += 4;
    }
    // Region C: i 32..47
    #pragma unroll 1
    for (int r = 0; r < 8; r++) {
        PIPE((do_chunk<2,3,2,3, 0,0,1,1, false>(bb, boff, abase, xq4c, I, acc)));
        I += 2;
    }
    // Region D: i 48..63
    #pragma unroll 1
    for (int r = 0; r < 4; r++) {
        PIPE((do_chunk<3,3,3,3, 0,1,2,3, false>(bb, boff, abase, xq4c, I, acc)));
        I += 4;
    }
    // Region E: linear term (chunk 40 — quad step fires: c & 3 == 0)
    PIPE((do_chunk<0,1,2,3, 0,0,0,0, true>(bb, boff, abase, xq4c, 0, acc)));

    // --- epilogue: a = bias + 0.5*acc; psi = prod cos(a) ---
    #pragma unroll
    for (int mb = 0; mb < 2; mb++) {
        float p0 = 1.0f, p1 = 1.0f;
        #pragma unroll
        for (int nb = 0; nb < 4; nb++) {
            int col = wn + nb * 8 + 2 * t4;
            #pragma unroll
            for (int cc = 0; cc < 2; cc++) {
                float bv = sbias[col + cc];
                p0 *= cos_poly(bv + 0.5f * acc[mb][nb][cc]);       // row g
                p1 *= cos_poly(bv + 0.5f * acc[mb][nb][2 + cc]);   // row g+8
            }
        }
        p0 *= __shfl_xor_sync(0xFFFFFFFFu, p0, 1);
        p0 *= __shfl_xor_sync(0xFFFFFFFFu, p0, 2);
        p1 *= __shfl_xor_sync(0xFFFFFFFFu, p1, 1);
        p1 *= __shfl_xor_sync(0xFFFFFFFFu, p1, 2);
        if (t4 == 0) {
            spart[(rb0 + 16 * mb) * 4 + (w & 3)]     = p0;
            spart[(rb0 + 16 * mb + 8) * 4 + (w & 3)] = p1;
        }
    }
    __syncthreads();
    if (tid < kMTile) {
        out[m0 + tid] = spart[tid * 4 + 0] * spart[tid * 4 + 1]
                      * spart[tid * 4 + 2] * spart[tid * 4 + 3];
    }
}

// ---------------------------------------------------------------------------
// launch
// ---------------------------------------------------------------------------
extern "C" void kernel_launch(void* const* d_in, const int* in_sizes, int n_in,
                              void* d_out, int out_size) {
    const float* x    = (const float*)d_in[0];   // (16384, 64)
    const float* w1   = (const float*)d_in[1];   // (64, 128)
    const float* w2   = (const float*)d_in[2];   // (128, 64, 64)
    const float* bias = (const float*)d_in[3];   // (128,)
    float* out = (float*)d_out;                  // (16384,)

    cudaFuncSetAttribute(rbm_main_kernel,
                         cudaFuncAttributeMaxDynamicSharedMemorySize, SMEM_TOTAL);

    prep_kernel<<<328, 256>>>(w2, w1);           // 41*8192/4/256
    rbm_main_kernel<<<16384 / kMTile, kThreads, SMEM_TOTAL>>>(x, bias, out);
}